// round 2
// baseline (speedup 1.0000x reference)
#include <cuda_runtime.h>
#include <math.h>

#define N_TOK 4096
#define DM 1024
#define NHEADS 16
#define DH 64

// Scratch (allocation-free rule: __device__ globals)
__device__ float g_q[N_TOK * DM];
__device__ float g_k[N_TOK * DM];
__device__ float g_v[N_TOK * DM];
__device__ float g_o[N_TOK * DM];

// ---------------------------------------------------------------------------
// Tiled SGEMM: C[MxN] = A[MxK] @ B[KxN], all row-major, M,N,K multiples of 64/16
// BM=BN=64, BK=16, 256 threads, 4x4 micro-tile per thread.
// ---------------------------------------------------------------------------
__global__ __launch_bounds__(256) void sgemm_kernel(
    const float* __restrict__ A, const float* __restrict__ B,
    float* __restrict__ C, int M, int N, int K)
{
    __shared__ float As[64][16];
    __shared__ float Bs[16][64];

    const int tid = threadIdx.x;
    const int m0 = blockIdx.y * 64;
    const int n0 = blockIdx.x * 64;
    const int r0 = (tid >> 4) << 2;   // 16 row-groups * 4 rows
    const int c0 = (tid & 15) << 2;   // 16 col-groups * 4 cols

    const int arow = tid >> 2, ac4 = tid & 3;     // A tile: 64 rows x 4 float4
    const int brow = tid >> 4, bc4 = tid & 15;    // B tile: 16 rows x 16 float4

    float acc[4][4] = {};

    for (int k0 = 0; k0 < K; k0 += 16) {
        *(float4*)&As[arow][ac4 * 4] =
            *(const float4*)&A[(size_t)(m0 + arow) * K + k0 + ac4 * 4];
        *(float4*)&Bs[brow][bc4 * 4] =
            *(const float4*)&B[(size_t)(k0 + brow) * N + n0 + bc4 * 4];
        __syncthreads();

#pragma unroll
        for (int kk = 0; kk < 16; kk++) {
            float4 b = *(const float4*)&Bs[kk][c0];
            float a0 = As[r0 + 0][kk];
            float a1 = As[r0 + 1][kk];
            float a2 = As[r0 + 2][kk];
            float a3 = As[r0 + 3][kk];
            acc[0][0] += a0 * b.x; acc[0][1] += a0 * b.y; acc[0][2] += a0 * b.z; acc[0][3] += a0 * b.w;
            acc[1][0] += a1 * b.x; acc[1][1] += a1 * b.y; acc[1][2] += a1 * b.z; acc[1][3] += a1 * b.w;
            acc[2][0] += a2 * b.x; acc[2][1] += a2 * b.y; acc[2][2] += a2 * b.z; acc[2][3] += a2 * b.w;
            acc[3][0] += a3 * b.x; acc[3][1] += a3 * b.y; acc[3][2] += a3 * b.z; acc[3][3] += a3 * b.w;
        }
        __syncthreads();
    }

#pragma unroll
    for (int i = 0; i < 4; i++) {
        float4 cv = make_float4(acc[i][0], acc[i][1], acc[i][2], acc[i][3]);
        *(float4*)&C[(size_t)(m0 + r0 + i) * N + n0 + c0] = cv;
    }
}

// ---------------------------------------------------------------------------
// L2-normalize each 64-float (token, head) chunk of q and k in place.
// One warp per chunk.  Matches F.normalize: x / max(||x||, 1e-12).
// ---------------------------------------------------------------------------
__global__ __launch_bounds__(256) void l2norm_kernel(float* __restrict__ q,
                                                     float* __restrict__ k)
{
    const int gwarp = (blockIdx.x * 256 + threadIdx.x) >> 5;
    const int lane = threadIdx.x & 31;
    float* buf = (gwarp < N_TOK * NHEADS) ? q : k;
    const int w = gwarp & (N_TOK * NHEADS - 1);  // 65536 chunks per buffer (pow2)
    const size_t base = (size_t)w * DH;

    float2 val = *(float2*)&buf[base + lane * 2];
    float ss = val.x * val.x + val.y * val.y;
#pragma unroll
    for (int off = 16; off > 0; off >>= 1)
        ss += __shfl_xor_sync(0xffffffffu, ss, off);
    float inv = 1.0f / fmaxf(sqrtf(ss), 1e-12f);
    val.x *= inv;
    val.y *= inv;
    *(float2*)&buf[base + lane * 2] = val;
}

// ---------------------------------------------------------------------------
// Causal flash attention, fp32. One block per (q-tile of 64, head).
// 256 threads; thread owns a 4(row)x4(col) micro-tile of the 64x64 S tile
// and a 4(row)x4(dh-col) micro-tile of the O accumulator.
// K tile stored transposed + float4-swizzled so score-phase b-loads are
// conflict-free float4.  P tile reuses the K buffer (score regs bridge).
// Static smem: 3 * 64*64*4 = 49152 B (exactly the 48KB static limit).
// ---------------------------------------------------------------------------
__global__ __launch_bounds__(256, 2) void attn_kernel(
    const float* __restrict__ qg, const float* __restrict__ kg,
    const float* __restrict__ vg, float* __restrict__ og)
{
    __shared__ float Qs[64 * 64];
    __shared__ float Vs[64 * 64];
    __shared__ float KP[64 * 64];  // Kt (swizzled) during scores; Ps during PV

    const int tid = threadIdx.x;
    const int h = blockIdx.y;
    const int qi = gridDim.x - 1 - blockIdx.x;  // heavy tiles launch first
    const int q0 = qi * 64;
    const int r0 = (tid >> 4) << 2;
    const int c0 = (tid & 15) << 2;
    const size_t hoff = (size_t)h * DH;

    // Load Q tile (64 rows x 64 floats), plain layout.
#pragma unroll
    for (int it = 0; it < 4; it++) {
        int idx = tid + 256 * it;
        int row = idx >> 4, c4 = idx & 15;
        *(float4*)&Qs[row * 64 + c4 * 4] =
            *(const float4*)&qg[(size_t)(q0 + row) * DM + hoff + c4 * 4];
    }

    float m_run[4], l_run[4], O[4][4];
#pragma unroll
    for (int i = 0; i < 4; i++) {
        m_run[i] = -1e30f;
        l_run[i] = 0.0f;
#pragma unroll
        for (int j = 0; j < 4; j++) O[i][j] = 0.0f;
    }

    for (int jt = 0; jt <= qi; jt++) {
        const int kv0 = jt * 64;
        __syncthreads();  // previous tile's PV (reads Vs/KP) is complete

        // Load K transposed + swizzled: element K[key][d] ->
        //   KP[d*64 + (((key>>2) ^ (d&15)) << 2) + (key&3)]
        // Load V plain: Vs[key*64 + d]
#pragma unroll
        for (int it = 0; it < 4; it++) {
            int idx = tid + 256 * it;
            int key = idx >> 4, d4 = idx & 15;
            const size_t gbase = (size_t)(kv0 + key) * DM + hoff + d4 * 4;
            float4 kv4 = *(const float4*)&kg[gbase];
            int key4 = key >> 2, kin = key & 3;
            int d = d4 * 4;
            KP[(d + 0) * 64 + ((key4 ^ ((d + 0) & 15)) << 2) + kin] = kv4.x;
            KP[(d + 1) * 64 + ((key4 ^ ((d + 1) & 15)) << 2) + kin] = kv4.y;
            KP[(d + 2) * 64 + ((key4 ^ ((d + 2) & 15)) << 2) + kin] = kv4.z;
            KP[(d + 3) * 64 + ((key4 ^ ((d + 3) & 15)) << 2) + kin] = kv4.w;
            *(float4*)&Vs[key * 64 + d4 * 4] = *(const float4*)&vg[gbase];
        }
        __syncthreads();

        // ---- scores: s[i][j] = sum_d Q[r0+i][d] * K[c0+j][d] ----
        float s[4][4] = {};
#pragma unroll
        for (int kk = 0; kk < 64; kk += 4) {
            float4 a[4], b[4];
#pragma unroll
            for (int i = 0; i < 4; i++)
                a[i] = *(const float4*)&Qs[(r0 + i) * 64 + kk];
#pragma unroll
            for (int u = 0; u < 4; u++) {
                int d = kk + u;
                b[u] = *(const float4*)&KP[d * 64 + (((c0 >> 2) ^ (d & 15)) << 2)];
            }
#pragma unroll
            for (int i = 0; i < 4; i++) {
                const float* ai = (const float*)&a[i];
#pragma unroll
                for (int u = 0; u < 4; u++) {
                    const float* bu = (const float*)&b[u];
                    float av = ai[u];
                    s[i][0] += av * bu[0];
                    s[i][1] += av * bu[1];
                    s[i][2] += av * bu[2];
                    s[i][3] += av * bu[3];
                }
            }
        }

        // ---- online softmax (rows shared by 16 consecutive lanes) ----
        const bool diag = (jt == qi);
        float p[4][4];
#pragma unroll
        for (int i = 0; i < 4; i++) {
            float mx = -1e30f;
#pragma unroll
            for (int j = 0; j < 4; j++) {
                float sv = s[i][j] * 8.0f;
                if (diag && (c0 + j > r0 + i)) sv = -1e30f;
                s[i][j] = sv;
                mx = fmaxf(mx, sv);
            }
#pragma unroll
            for (int off = 1; off < 16; off <<= 1)
                mx = fmaxf(mx, __shfl_xor_sync(0xffffffffu, mx, off));
            float m_new = fmaxf(m_run[i], mx);
            float fac = __expf(m_run[i] - m_new);
            m_run[i] = m_new;
            float ts = 0.0f;
#pragma unroll
            for (int j = 0; j < 4; j++) {
                float pv = __expf(s[i][j] - m_new);
                p[i][j] = pv;
                ts += pv;
            }
#pragma unroll
            for (int off = 1; off < 16; off <<= 1)
                ts += __shfl_xor_sync(0xffffffffu, ts, off);
            l_run[i] = l_run[i] * fac + ts;
#pragma unroll
            for (int j = 0; j < 4; j++) O[i][j] *= fac;
        }

        __syncthreads();  // all score-phase KP reads done; reuse as Ps
#pragma unroll
        for (int i = 0; i < 4; i++)
            *(float4*)&KP[(r0 + i) * 64 + c0] =
                make_float4(p[i][0], p[i][1], p[i][2], p[i][3]);
        __syncthreads();

        // ---- PV: O[i][j] += sum_key P[r0+i][key] * V[key][c0+j] ----
#pragma unroll
        for (int key = 0; key < 64; key += 4) {
            float4 pv[4], vv[4];
#pragma unroll
            for (int i = 0; i < 4; i++)
                pv[i] = *(const float4*)&KP[(r0 + i) * 64 + key];
#pragma unroll
            for (int u = 0; u < 4; u++)
                vv[u] = *(const float4*)&Vs[(key + u) * 64 + c0];
#pragma unroll
            for (int i = 0; i < 4; i++) {
                const float* pi = (const float*)&pv[i];
#pragma unroll
                for (int u = 0; u < 4; u++) {
                    const float* vu = (const float*)&vv[u];
                    float pval = pi[u];
                    O[i][0] += pval * vu[0];
                    O[i][1] += pval * vu[1];
                    O[i][2] += pval * vu[2];
                    O[i][3] += pval * vu[3];
                }
            }
        }
    }

#pragma unroll
    for (int i = 0; i < 4; i++) {
        float inv = 1.0f / l_run[i];
        float4 ov = make_float4(O[i][0] * inv, O[i][1] * inv,
                                O[i][2] * inv, O[i][3] * inv);
        *(float4*)&og[(size_t)(q0 + r0 + i) * DM + hoff + c0] = ov;
    }
}

// ---------------------------------------------------------------------------
extern "C" void kernel_launch(void* const* d_in, const int* in_sizes, int n_in,
                              void* d_out, int out_size)
{
    const float* x  = (const float*)d_in[0];
    const float* Wq = (const float*)d_in[1];
    const float* Wk = (const float*)d_in[2];
    const float* Wv = (const float*)d_in[3];
    const float* Wo = (const float*)d_in[4];
    float* out = (float*)d_out;

    float *q, *k, *v, *o;
    cudaGetSymbolAddress((void**)&q, g_q);
    cudaGetSymbolAddress((void**)&k, g_k);
    cudaGetSymbolAddress((void**)&v, g_v);
    cudaGetSymbolAddress((void**)&o, g_o);

    dim3 gemm_grid(DM / 64, N_TOK / 64);
    sgemm_kernel<<<gemm_grid, 256>>>(x, Wq, q, N_TOK, DM, DM);
    sgemm_kernel<<<gemm_grid, 256>>>(x, Wk, k, N_TOK, DM, DM);
    sgemm_kernel<<<gemm_grid, 256>>>(x, Wv, v, N_TOK, DM, DM);

    l2norm_kernel<<<(2 * N_TOK * NHEADS) / 8, 256>>>(q, k);

    attn_kernel<<<dim3(N_TOK / 64, NHEADS), 256>>>(q, k, v, o);

    sgemm_kernel<<<gemm_grid, 256>>>(o, Wo, out, N_TOK, DM, DM);
}

// round 5
// speedup vs baseline: 1.2736x; 1.2736x over previous
#include <cuda_runtime.h>
#include <cuda_bf16.h>
#include <cstdint>
#include <math.h>

#define N_TOK 4096
#define DM 1024
#define NHEADS 16
#define DH 64

// ---------------------------------------------------------------------------
// Scratch (allocation-free rule: __device__ globals)
// ---------------------------------------------------------------------------
__device__ float g_q[N_TOK * DM];
__device__ float g_k[N_TOK * DM];
__device__ float g_v[N_TOK * DM];
__device__ float g_o[N_TOK * DM];

__device__ __nv_bfloat16 g_xh[N_TOK * DM];
__device__ __nv_bfloat16 g_xl[N_TOK * DM];
__device__ __nv_bfloat16 g_oh[N_TOK * DM];
__device__ __nv_bfloat16 g_ol[N_TOK * DM];
__device__ __nv_bfloat16 g_wth[4 * DM * DM];  // W^T hi: [w][n][k]
__device__ __nv_bfloat16 g_wtl[4 * DM * DM];  // W^T lo

// SW64 swizzle for 64-byte rows (8 bf16-16B columns cycle over banks)
#define SWZ64(o) ((o) ^ (((o) >> 3) & 0x30))

__device__ __forceinline__ uint32_t smem_u32(const void* p) {
    uint32_t a;
    asm("{ .reg .u64 t; cvta.to.shared.u64 t, %1; cvt.u32.u64 %0, t; }"
        : "=r"(a) : "l"(p));
    return a;
}

__device__ __forceinline__ void ldsm4(uint32_t addr, uint32_t r[4]) {
    asm volatile("ldmatrix.sync.aligned.m8n8.x4.shared.b16 {%0,%1,%2,%3}, [%4];"
                 : "=r"(r[0]), "=r"(r[1]), "=r"(r[2]), "=r"(r[3]) : "r"(addr));
}
__device__ __forceinline__ void ldsm2(uint32_t addr, uint32_t r[2]) {
    asm volatile("ldmatrix.sync.aligned.m8n8.x2.shared.b16 {%0,%1}, [%2];"
                 : "=r"(r[0]), "=r"(r[1]) : "r"(addr));
}
__device__ __forceinline__ void mma_bf16(float c[4], const uint32_t a[4],
                                         const uint32_t b[2]) {
    asm volatile(
        "mma.sync.aligned.m16n8k16.row.col.f32.bf16.bf16.f32 "
        "{%0,%1,%2,%3}, {%4,%5,%6,%7}, {%8,%9}, {%0,%1,%2,%3};"
        : "+f"(c[0]), "+f"(c[1]), "+f"(c[2]), "+f"(c[3])
        : "r"(a[0]), "r"(a[1]), "r"(a[2]), "r"(a[3]), "r"(b[0]), "r"(b[1]));
}

// ---------------------------------------------------------------------------
// Split fp32 -> (hi, lo) bf16, elementwise (for x and o).
// ---------------------------------------------------------------------------
__global__ __launch_bounds__(256) void split_kernel(
    const float* __restrict__ src, __nv_bfloat16* __restrict__ h,
    __nv_bfloat16* __restrict__ l)
{
    int i = blockIdx.x * 256 + threadIdx.x;  // one float4 per thread
    float4 v = ((const float4*)src)[i];
    __nv_bfloat16 h0 = __float2bfloat16(v.x);
    __nv_bfloat16 h1 = __float2bfloat16(v.y);
    __nv_bfloat16 h2 = __float2bfloat16(v.z);
    __nv_bfloat16 h3 = __float2bfloat16(v.w);
    __nv_bfloat16 l0 = __float2bfloat16(v.x - __bfloat162float(h0));
    __nv_bfloat16 l1 = __float2bfloat16(v.y - __bfloat162float(h1));
    __nv_bfloat16 l2 = __float2bfloat16(v.z - __bfloat162float(h2));
    __nv_bfloat16 l3 = __float2bfloat16(v.w - __bfloat162float(h3));
    ((__nv_bfloat162*)h)[2 * i + 0] = __nv_bfloat162(h0, h1);
    ((__nv_bfloat162*)h)[2 * i + 1] = __nv_bfloat162(h2, h3);
    ((__nv_bfloat162*)l)[2 * i + 0] = __nv_bfloat162(l0, l1);
    ((__nv_bfloat162*)l)[2 * i + 1] = __nv_bfloat162(l2, l3);
}

// ---------------------------------------------------------------------------
// Transpose + split all 4 weight matrices: out[w][n][k] = split(W_w[k][n]).
// ---------------------------------------------------------------------------
__global__ __launch_bounds__(256) void tsplit_kernel(
    const float* __restrict__ W0, const float* __restrict__ W1,
    const float* __restrict__ W2, const float* __restrict__ W3,
    __nv_bfloat16* __restrict__ H, __nv_bfloat16* __restrict__ L)
{
    const float* W = (blockIdx.z == 0) ? W0 : (blockIdx.z == 1) ? W1
                   : (blockIdx.z == 2) ? W2 : W3;
    __nv_bfloat16* h = H + (size_t)blockIdx.z * DM * DM;
    __nv_bfloat16* l = L + (size_t)blockIdx.z * DM * DM;
    __shared__ float t[32][33];
    const int bx = blockIdx.x * 32;  // n block
    const int by = blockIdx.y * 32;  // k block
    const int tx = threadIdx.x;
    for (int j = threadIdx.y; j < 32; j += 8)
        t[j][tx] = W[(size_t)(by + j) * DM + bx + tx];
    __syncthreads();
    for (int j = threadIdx.y; j < 32; j += 8) {
        float v = t[tx][j];  // = W[by+tx][bx+j]
        __nv_bfloat16 hv = __float2bfloat16(v);
        __nv_bfloat16 lv = __float2bfloat16(v - __bfloat162float(hv));
        size_t idx = (size_t)(bx + j) * DM + by + tx;
        h[idx] = hv;
        l[idx] = lv;
    }
}

// ---------------------------------------------------------------------------
// HMMA split-bf16 GEMM: C[M x 1024] = A @ B^T.
// A hi/lo: [M][1024] row-major bf16; B hi/lo: [1024 n][1024 k] row-major bf16.
// CTA tile 128x128, BK=32, 8 warps (2m x 4n), warp tile 64x32.
// C(fp32) += Ah*Bh + Ah*Bl + Al*Bh via mma.sync m16n8k16.
// ---------------------------------------------------------------------------
__global__ __launch_bounds__(256, 2) void gemm_mma_kernel(
    const __nv_bfloat16* __restrict__ Ah, const __nv_bfloat16* __restrict__ Al,
    const __nv_bfloat16* __restrict__ Bh, const __nv_bfloat16* __restrict__ Bl,
    float* __restrict__ C)
{
    __shared__ __nv_bfloat16 sAh[128 * 32];
    __shared__ __nv_bfloat16 sAl[128 * 32];
    __shared__ __nv_bfloat16 sBh[128 * 32];
    __shared__ __nv_bfloat16 sBl[128 * 32];

    const int tid = threadIdx.x;
    const int wid = tid >> 5, lane = tid & 31;
    const int wm = wid & 1, wn = wid >> 1;  // 2 x 4 warp grid
    const int m0 = blockIdx.y * 128, n0 = blockIdx.x * 128;

    const uint32_t uAh = smem_u32(sAh), uAl = smem_u32(sAl);
    const uint32_t uBh = smem_u32(sBh), uBl = smem_u32(sBl);

    // ldmatrix per-lane address components
    const int a_row = ((lane >> 3) & 1) * 8 + (lane & 7);
    const int a_kb  = (lane >> 4) * 16;           // byte offset within 32-bf16 row
    const int l15 = lane & 15;
    const int b_row = l15 & 7;
    const int b_kb  = (l15 >> 3) * 16;

    float c[4][4][4] = {};

    for (int kc = 0; kc < 32; kc++) {
        const int k0 = kc * 32;
        // ---- load 4 tiles (each 128 rows x 32 bf16 = 8KB), SW64 swizzled ----
#pragma unroll
        for (int i = 0; i < 2; i++) {
            const int cchunk = tid + 256 * i;        // 16B chunk id (0..511)
            const int row = cchunk >> 2, kb16 = cchunk & 3;
            const uint32_t so = SWZ64(row * 64 + kb16 * 16);
            const size_t ga = (size_t)(m0 + row) * DM + k0 + kb16 * 8;
            const size_t gb = (size_t)(n0 + row) * DM + k0 + kb16 * 8;
            *(float4*)((char*)sAh + so) = *(const float4*)(Ah + ga);
            *(float4*)((char*)sAl + so) = *(const float4*)(Al + ga);
            *(float4*)((char*)sBh + so) = *(const float4*)(Bh + gb);
            *(float4*)((char*)sBl + so) = *(const float4*)(Bl + gb);
        }
        __syncthreads();

#pragma unroll
        for (int ks = 0; ks < 2; ks++) {
            uint32_t bh[4][2], bl[4][2];
#pragma unroll
            for (int nt = 0; nt < 4; nt++) {
                const uint32_t bo =
                    SWZ64((wn * 32 + nt * 8 + b_row) * 64 + ks * 32 + b_kb);
                ldsm2(uBh + bo, bh[nt]);
                ldsm2(uBl + bo, bl[nt]);
            }
#pragma unroll
            for (int mt = 0; mt < 4; mt++) {
                uint32_t ah[4], al[4];
                const uint32_t ao =
                    SWZ64((wm * 64 + mt * 16 + a_row) * 64 + ks * 32 + a_kb);
                ldsm4(uAh + ao, ah);
                ldsm4(uAl + ao, al);
#pragma unroll
                for (int nt = 0; nt < 4; nt++) {
                    mma_bf16(c[mt][nt], ah, bh[nt]);
                    mma_bf16(c[mt][nt], ah, bl[nt]);
                    mma_bf16(c[mt][nt], al, bh[nt]);
                }
            }
        }
        __syncthreads();
    }

    // ---- epilogue: write fp32 C ----
    const int gq = lane >> 2, tq = lane & 3;
#pragma unroll
    for (int mt = 0; mt < 4; mt++) {
#pragma unroll
        for (int nt = 0; nt < 4; nt++) {
            const int row = m0 + wm * 64 + mt * 16 + gq;
            const int col = n0 + wn * 32 + nt * 8 + tq * 2;
            *(float2*)&C[(size_t)row * DM + col] =
                make_float2(c[mt][nt][0], c[mt][nt][1]);
            *(float2*)&C[(size_t)(row + 8) * DM + col] =
                make_float2(c[mt][nt][2], c[mt][nt][3]);
        }
    }
}

// ---------------------------------------------------------------------------
// Causal flash attention, fp32 SIMT, L2-normalization of q/k fused into the
// tile loads. One block per (q-tile of 64, head), 256 threads, 4x4 micro-tile.
// ---------------------------------------------------------------------------
__global__ __launch_bounds__(256, 2) void attn_kernel(
    const float* __restrict__ qg, const float* __restrict__ kg,
    const float* __restrict__ vg, float* __restrict__ og)
{
    __shared__ float Qs[64 * 64];
    __shared__ float Vs[64 * 64];
    __shared__ float KP[64 * 64];

    const int tid = threadIdx.x;
    const int h = blockIdx.y;
    const int qi = gridDim.x - 1 - blockIdx.x;
    const int q0 = qi * 64;
    const int r0 = (tid >> 4) << 2;
    const int c0 = (tid & 15) << 2;
    const size_t hoff = (size_t)h * DH;

#pragma unroll
    for (int it = 0; it < 4; it++) {
        int idx = tid + 256 * it;
        int row = idx >> 4, c4 = idx & 15;
        float4 qv = *(const float4*)&qg[(size_t)(q0 + row) * DM + hoff + c4 * 4];
        float ss = qv.x * qv.x + qv.y * qv.y + qv.z * qv.z + qv.w * qv.w;
#pragma unroll
        for (int off = 1; off < 16; off <<= 1)
            ss += __shfl_xor_sync(0xffffffffu, ss, off);
        float inv = 1.0f / fmaxf(sqrtf(ss), 1e-12f);
        qv.x *= inv; qv.y *= inv; qv.z *= inv; qv.w *= inv;
        *(float4*)&Qs[row * 64 + c4 * 4] = qv;
    }

    float m_run[4], l_run[4], O[4][4];
#pragma unroll
    for (int i = 0; i < 4; i++) {
        m_run[i] = -1e30f;
        l_run[i] = 0.0f;
#pragma unroll
        for (int j = 0; j < 4; j++) O[i][j] = 0.0f;
    }

    for (int jt = 0; jt <= qi; jt++) {
        const int kv0 = jt * 64;
        __syncthreads();

#pragma unroll
        for (int it = 0; it < 4; it++) {
            int idx = tid + 256 * it;
            int key = idx >> 4, d4 = idx & 15;
            const size_t gbase = (size_t)(kv0 + key) * DM + hoff + d4 * 4;
            float4 kv4 = *(const float4*)&kg[gbase];
            float ss = kv4.x * kv4.x + kv4.y * kv4.y + kv4.z * kv4.z + kv4.w * kv4.w;
#pragma unroll
            for (int off = 1; off < 16; off <<= 1)
                ss += __shfl_xor_sync(0xffffffffu, ss, off);
            float inv = 1.0f / fmaxf(sqrtf(ss), 1e-12f);
            kv4.x *= inv; kv4.y *= inv; kv4.z *= inv; kv4.w *= inv;
            int key4 = key >> 2, kin = key & 3;
            int d = d4 * 4;
            KP[(d + 0) * 64 + ((key4 ^ ((d + 0) & 15)) << 2) + kin] = kv4.x;
            KP[(d + 1) * 64 + ((key4 ^ ((d + 1) & 15)) << 2) + kin] = kv4.y;
            KP[(d + 2) * 64 + ((key4 ^ ((d + 2) & 15)) << 2) + kin] = kv4.z;
            KP[(d + 3) * 64 + ((key4 ^ ((d + 3) & 15)) << 2) + kin] = kv4.w;
            *(float4*)&Vs[key * 64 + d4 * 4] = *(const float4*)&vg[gbase];
        }
        __syncthreads();

        float s[4][4] = {};
#pragma unroll
        for (int kk = 0; kk < 64; kk += 4) {
            float4 a[4], b[4];
#pragma unroll
            for (int i = 0; i < 4; i++)
                a[i] = *(const float4*)&Qs[(r0 + i) * 64 + kk];
#pragma unroll
            for (int u = 0; u < 4; u++) {
                int d = kk + u;
                b[u] = *(const float4*)&KP[d * 64 + (((c0 >> 2) ^ (d & 15)) << 2)];
            }
#pragma unroll
            for (int i = 0; i < 4; i++) {
                const float* ai = (const float*)&a[i];
#pragma unroll
                for (int u = 0; u < 4; u++) {
                    const float* bu = (const float*)&b[u];
                    float av = ai[u];
                    s[i][0] += av * bu[0];
                    s[i][1] += av * bu[1];
                    s[i][2] += av * bu[2];
                    s[i][3] += av * bu[3];
                }
            }
        }

        const bool diag = (jt == qi);
        float p[4][4];
#pragma unroll
        for (int i = 0; i < 4; i++) {
            float mx = -1e30f;
#pragma unroll
            for (int j = 0; j < 4; j++) {
                float sv = s[i][j] * 8.0f;
                if (diag && (c0 + j > r0 + i)) sv = -1e30f;
                s[i][j] = sv;
                mx = fmaxf(mx, sv);
            }
#pragma unroll
            for (int off = 1; off < 16; off <<= 1)
                mx = fmaxf(mx, __shfl_xor_sync(0xffffffffu, mx, off));
            float m_new = fmaxf(m_run[i], mx);
            float fac = __expf(m_run[i] - m_new);
            m_run[i] = m_new;
            float ts = 0.0f;
#pragma unroll
            for (int j = 0; j < 4; j++) {
                float pv = __expf(s[i][j] - m_new);
                p[i][j] = pv;
                ts += pv;
            }
#pragma unroll
            for (int off = 1; off < 16; off <<= 1)
                ts += __shfl_xor_sync(0xffffffffu, ts, off);
            l_run[i] = l_run[i] * fac + ts;
#pragma unroll
            for (int j = 0; j < 4; j++) O[i][j] *= fac;
        }

        __syncthreads();
#pragma unroll
        for (int i = 0; i < 4; i++)
            *(float4*)&KP[(r0 + i) * 64 + c0] =
                make_float4(p[i][0], p[i][1], p[i][2], p[i][3]);
        __syncthreads();

#pragma unroll
        for (int key = 0; key < 64; key += 4) {
            float4 pv[4], vv[4];
#pragma unroll
            for (int i = 0; i < 4; i++)
                pv[i] = *(const float4*)&KP[(r0 + i) * 64 + key];
#pragma unroll
            for (int u = 0; u < 4; u++)
                vv[u] = *(const float4*)&Vs[(key + u) * 64 + c0];
#pragma unroll
            for (int i = 0; i < 4; i++) {
                const float* pi = (const float*)&pv[i];
#pragma unroll
                for (int u = 0; u < 4; u++) {
                    const float* vu = (const float*)&vv[u];
                    float pval = pi[u];
                    O[i][0] += pval * vu[0];
                    O[i][1] += pval * vu[1];
                    O[i][2] += pval * vu[2];
                    O[i][3] += pval * vu[3];
                }
            }
        }
    }

#pragma unroll
    for (int i = 0; i < 4; i++) {
        float inv = 1.0f / l_run[i];
        float4 ov = make_float4(O[i][0] * inv, O[i][1] * inv,
                                O[i][2] * inv, O[i][3] * inv);
        *(float4*)&og[(size_t)(q0 + r0 + i) * DM + hoff + c0] = ov;
    }
}

// ---------------------------------------------------------------------------
extern "C" void kernel_launch(void* const* d_in, const int* in_sizes, int n_in,
                              void* d_out, int out_size)
{
    const float* x  = (const float*)d_in[0];
    const float* Wq = (const float*)d_in[1];
    const float* Wk = (const float*)d_in[2];
    const float* Wv = (const float*)d_in[3];
    const float* Wo = (const float*)d_in[4];
    float* out = (float*)d_out;

    float *q, *k, *v, *o;
    cudaGetSymbolAddress((void**)&q, g_q);
    cudaGetSymbolAddress((void**)&k, g_k);
    cudaGetSymbolAddress((void**)&v, g_v);
    cudaGetSymbolAddress((void**)&o, g_o);
    __nv_bfloat16 *xh, *xl, *oh, *ol, *wth, *wtl;
    cudaGetSymbolAddress((void**)&xh, g_xh);
    cudaGetSymbolAddress((void**)&xl, g_xl);
    cudaGetSymbolAddress((void**)&oh, g_oh);
    cudaGetSymbolAddress((void**)&ol, g_ol);
    cudaGetSymbolAddress((void**)&wth, g_wth);
    cudaGetSymbolAddress((void**)&wtl, g_wtl);

    const int nvec = N_TOK * DM / 4;
    dim3 gemm_grid(DM / 128, N_TOK / 128);

    split_kernel<<<nvec / 256, 256>>>(x, xh, xl);
    tsplit_kernel<<<dim3(32, 32, 4), dim3(32, 8)>>>(Wq, Wk, Wv, Wo, wth, wtl);
    gemm_mma_kernel<<<gemm_grid, 256>>>(xh, xl, wth + 0 * (size_t)DM * DM, wtl + 0 * (size_t)DM * DM, q);
    gemm_mma_kernel<<<gemm_grid, 256>>>(xh, xl, wth + 1 * (size_t)DM * DM, wtl + 1 * (size_t)DM * DM, k);
    gemm_mma_kernel<<<gemm_grid, 256>>>(xh, xl, wth + 2 * (size_t)DM * DM, wtl + 2 * (size_t)DM * DM, v);
    attn_kernel<<<dim3(N_TOK / 64, NHEADS), 256>>>(q, k, v, o);
    split_kernel<<<nvec / 256, 256>>>(o, oh, ol);
    gemm_mma_kernel<<<gemm_grid, 256>>>(oh, ol, wth + 3 * (size_t)DM * DM, wtl + 3 * (size_t)DM * DM, out);
}

// round 6
// speedup vs baseline: 2.0238x; 1.5890x over previous
#include <cuda_runtime.h>
#include <cuda_bf16.h>
#include <cstdint>
#include <math.h>

#define N_TOK 4096
#define DM 1024
#define NHEADS 16
#define DH 64

// ---------------------------------------------------------------------------
// Scratch (allocation-free rule: __device__ globals)
// ---------------------------------------------------------------------------
__device__ float g_q[N_TOK * DM];
__device__ float g_k[N_TOK * DM];
__device__ float g_v[N_TOK * DM];
__device__ float g_o[N_TOK * DM];

__device__ __nv_bfloat16 g_xh[N_TOK * DM];
__device__ __nv_bfloat16 g_xl[N_TOK * DM];
__device__ __nv_bfloat16 g_oh[N_TOK * DM];
__device__ __nv_bfloat16 g_ol[N_TOK * DM];
__device__ __nv_bfloat16 g_wth[4 * DM * DM];  // W^T hi: [w][n][k]
__device__ __nv_bfloat16 g_wtl[4 * DM * DM];  // W^T lo

#define SWZ64(o)  ((o) ^ (((o) >> 3) & 0x30))
#define SWZ128(o) ((o) ^ (((o) >> 3) & 0x70))

__device__ __forceinline__ uint32_t smem_u32(const void* p) {
    uint32_t a;
    asm("{ .reg .u64 t; cvta.to.shared.u64 t, %1; cvt.u32.u64 %0, t; }"
        : "=r"(a) : "l"(p));
    return a;
}

__device__ __forceinline__ void ldsm4(uint32_t addr, uint32_t r[4]) {
    asm volatile("ldmatrix.sync.aligned.m8n8.x4.shared.b16 {%0,%1,%2,%3}, [%4];"
                 : "=r"(r[0]), "=r"(r[1]), "=r"(r[2]), "=r"(r[3]) : "r"(addr));
}
__device__ __forceinline__ void ldsm4t(uint32_t addr, uint32_t r[4]) {
    asm volatile("ldmatrix.sync.aligned.m8n8.x4.trans.shared.b16 {%0,%1,%2,%3}, [%4];"
                 : "=r"(r[0]), "=r"(r[1]), "=r"(r[2]), "=r"(r[3]) : "r"(addr));
}
__device__ __forceinline__ void ldsm2(uint32_t addr, uint32_t r[2]) {
    asm volatile("ldmatrix.sync.aligned.m8n8.x2.shared.b16 {%0,%1}, [%2];"
                 : "=r"(r[0]), "=r"(r[1]) : "r"(addr));
}
__device__ __forceinline__ void mma_bf16(float c[4], const uint32_t a[4],
                                         const uint32_t b[2]) {
    asm volatile(
        "mma.sync.aligned.m16n8k16.row.col.f32.bf16.bf16.f32 "
        "{%0,%1,%2,%3}, {%4,%5,%6,%7}, {%8,%9}, {%0,%1,%2,%3};"
        : "+f"(c[0]), "+f"(c[1]), "+f"(c[2]), "+f"(c[3])
        : "r"(a[0]), "r"(a[1]), "r"(a[2]), "r"(a[3]), "r"(b[0]), "r"(b[1]));
}
// pack two fp32 into bf16x2 (lo = a, hi = b), round-to-nearest
__device__ __forceinline__ uint32_t pack2(float a, float b) {
    uint32_t r;
    asm("cvt.rn.bf16x2.f32 %0, %1, %2;" : "=r"(r) : "f"(b), "f"(a));
    return r;
}
__device__ __forceinline__ float bfr(float x) {  // value after bf16 rounding
    return __bfloat162float(__float2bfloat16(x));
}

// ---------------------------------------------------------------------------
// Split fp32 -> (hi, lo) bf16, elementwise (for x and o).
// ---------------------------------------------------------------------------
__global__ __launch_bounds__(256) void split_kernel(
    const float* __restrict__ src, __nv_bfloat16* __restrict__ h,
    __nv_bfloat16* __restrict__ l)
{
    int i = blockIdx.x * 256 + threadIdx.x;
    float4 v = ((const float4*)src)[i];
    ((uint32_t*)h)[2 * i + 0] = pack2(v.x, v.y);
    ((uint32_t*)h)[2 * i + 1] = pack2(v.z, v.w);
    ((uint32_t*)l)[2 * i + 0] = pack2(v.x - bfr(v.x), v.y - bfr(v.y));
    ((uint32_t*)l)[2 * i + 1] = pack2(v.z - bfr(v.z), v.w - bfr(v.w));
}

// ---------------------------------------------------------------------------
// Transpose + split all 4 weight matrices: out[w][n][k] = split(W_w[k][n]).
// ---------------------------------------------------------------------------
__global__ __launch_bounds__(256) void tsplit_kernel(
    const float* __restrict__ W0, const float* __restrict__ W1,
    const float* __restrict__ W2, const float* __restrict__ W3,
    __nv_bfloat16* __restrict__ H, __nv_bfloat16* __restrict__ L)
{
    const float* W = (blockIdx.z == 0) ? W0 : (blockIdx.z == 1) ? W1
                   : (blockIdx.z == 2) ? W2 : W3;
    __nv_bfloat16* h = H + (size_t)blockIdx.z * DM * DM;
    __nv_bfloat16* l = L + (size_t)blockIdx.z * DM * DM;
    __shared__ float t[32][33];
    const int bx = blockIdx.x * 32;  // n block
    const int by = blockIdx.y * 32;  // k block
    const int tx = threadIdx.x;
    for (int j = threadIdx.y; j < 32; j += 8)
        t[j][tx] = W[(size_t)(by + j) * DM + bx + tx];
    __syncthreads();
    for (int j = threadIdx.y; j < 32; j += 8) {
        float v = t[tx][j];  // = W[by+tx][bx+j]
        __nv_bfloat16 hv = __float2bfloat16(v);
        __nv_bfloat16 lv = __float2bfloat16(v - __bfloat162float(hv));
        size_t idx = (size_t)(bx + j) * DM + by + tx;
        h[idx] = hv;
        l[idx] = lv;
    }
}

// ---------------------------------------------------------------------------
// HMMA split-bf16 GEMM: C[M x 1024] = A @ B^T  (unchanged from R5 — proven).
// ---------------------------------------------------------------------------
__global__ __launch_bounds__(256, 2) void gemm_mma_kernel(
    const __nv_bfloat16* __restrict__ Ah, const __nv_bfloat16* __restrict__ Al,
    const __nv_bfloat16* __restrict__ Bh, const __nv_bfloat16* __restrict__ Bl,
    float* __restrict__ C)
{
    __shared__ __nv_bfloat16 sAh[128 * 32];
    __shared__ __nv_bfloat16 sAl[128 * 32];
    __shared__ __nv_bfloat16 sBh[128 * 32];
    __shared__ __nv_bfloat16 sBl[128 * 32];

    const int tid = threadIdx.x;
    const int wid = tid >> 5, lane = tid & 31;
    const int wm = wid & 1, wn = wid >> 1;
    const int m0 = blockIdx.y * 128, n0 = blockIdx.x * 128;

    const uint32_t uAh = smem_u32(sAh), uAl = smem_u32(sAl);
    const uint32_t uBh = smem_u32(sBh), uBl = smem_u32(sBl);

    const int a_row = ((lane >> 3) & 1) * 8 + (lane & 7);
    const int a_kb  = (lane >> 4) * 16;
    const int l15 = lane & 15;
    const int b_row = l15 & 7;
    const int b_kb  = (l15 >> 3) * 16;

    float c[4][4][4] = {};

    for (int kc = 0; kc < 32; kc++) {
        const int k0 = kc * 32;
#pragma unroll
        for (int i = 0; i < 2; i++) {
            const int cchunk = tid + 256 * i;
            const int row = cchunk >> 2, kb16 = cchunk & 3;
            const uint32_t so = SWZ64(row * 64 + kb16 * 16);
            const size_t ga = (size_t)(m0 + row) * DM + k0 + kb16 * 8;
            const size_t gb = (size_t)(n0 + row) * DM + k0 + kb16 * 8;
            *(float4*)((char*)sAh + so) = *(const float4*)(Ah + ga);
            *(float4*)((char*)sAl + so) = *(const float4*)(Al + ga);
            *(float4*)((char*)sBh + so) = *(const float4*)(Bh + gb);
            *(float4*)((char*)sBl + so) = *(const float4*)(Bl + gb);
        }
        __syncthreads();

#pragma unroll
        for (int ks = 0; ks < 2; ks++) {
            uint32_t bh[4][2], bl[4][2];
#pragma unroll
            for (int nt = 0; nt < 4; nt++) {
                const uint32_t bo =
                    SWZ64((wn * 32 + nt * 8 + b_row) * 64 + ks * 32 + b_kb);
                ldsm2(uBh + bo, bh[nt]);
                ldsm2(uBl + bo, bl[nt]);
            }
#pragma unroll
            for (int mt = 0; mt < 4; mt++) {
                uint32_t ah[4], al[4];
                const uint32_t ao =
                    SWZ64((wm * 64 + mt * 16 + a_row) * 64 + ks * 32 + a_kb);
                ldsm4(uAh + ao, ah);
                ldsm4(uAl + ao, al);
#pragma unroll
                for (int nt = 0; nt < 4; nt++) {
                    mma_bf16(c[mt][nt], ah, bh[nt]);
                    mma_bf16(c[mt][nt], ah, bl[nt]);
                    mma_bf16(c[mt][nt], al, bh[nt]);
                }
            }
        }
        __syncthreads();
    }

    const int gq = lane >> 2, tq = lane & 3;
#pragma unroll
    for (int mt = 0; mt < 4; mt++) {
#pragma unroll
        for (int nt = 0; nt < 4; nt++) {
            const int row = m0 + wm * 64 + mt * 16 + gq;
            const int col = n0 + wn * 32 + nt * 8 + tq * 2;
            *(float2*)&C[(size_t)row * DM + col] =
                make_float2(c[mt][nt][0], c[mt][nt][1]);
            *(float2*)&C[(size_t)(row + 8) * DM + col] =
                make_float2(c[mt][nt][2], c[mt][nt][3]);
        }
    }
}

// ---------------------------------------------------------------------------
// Tensor-core causal flash attention (split-bf16, fp32 accum).
// Block = (q-tile of 128, head). 8 warps, warp owns m16 of S and O.
// KV tile = 64. l2norm of q/k fused into smem loads. Softmax in registers.
// Dynamic smem 64KB: Qh 16K | Ql 16K | Kh 8K | Kl 8K | Vh 8K | Vl 8K.
// ---------------------------------------------------------------------------
#define ATTN_SMEM 65536

__global__ __launch_bounds__(256, 1) void attn_mma_kernel(
    const float* __restrict__ qg, const float* __restrict__ kg,
    const float* __restrict__ vg, float* __restrict__ og)
{
    extern __shared__ char sm[];
    const uint32_t sb = smem_u32(sm);
    const uint32_t uQh = sb, uQl = sb + 16384;
    const uint32_t uKh = sb + 32768, uKl = sb + 40960;
    const uint32_t uVh = sb + 49152, uVl = sb + 57344;

    const int tid = threadIdx.x, wid = tid >> 5, lane = tid & 31;
    const int h = blockIdx.y;
    const int qi = gridDim.x - 1 - blockIdx.x;   // heavy tiles first
    const int q0 = qi * 128;
    const size_t hoff = (size_t)h * DH;

    // ---- load Q tile (128 x 64), l2-normalize rows, split, store swizzled ----
#pragma unroll
    for (int it = 0; it < 8; it++) {
        int idx = tid + 256 * it;
        int row = idx >> 4, c4 = idx & 15;
        float4 v = *(const float4*)&qg[(size_t)(q0 + row) * DM + hoff + c4 * 4];
        float ss = v.x * v.x + v.y * v.y + v.z * v.z + v.w * v.w;
#pragma unroll
        for (int off = 1; off < 16; off <<= 1)
            ss += __shfl_xor_sync(0xffffffffu, ss, off);
        float inv = 1.0f / fmaxf(sqrtf(ss), 1e-12f);
        v.x *= inv; v.y *= inv; v.z *= inv; v.w *= inv;
        uint32_t so = SWZ128(row * 128 + c4 * 8);
        uint2 hv = make_uint2(pack2(v.x, v.y), pack2(v.z, v.w));
        uint2 lv = make_uint2(pack2(v.x - bfr(v.x), v.y - bfr(v.y)),
                              pack2(v.z - bfr(v.z), v.w - bfr(v.w)));
        *(uint2*)(sm + so) = hv;
        *(uint2*)(sm + 16384 + so) = lv;
    }

    float m_run[2] = {-1e30f, -1e30f};
    float l_run[2] = {0.0f, 0.0f};
    float o[8][4] = {};

    const int row_lo = q0 + wid * 16 + (lane >> 2);  // half 0 row (global)
    const int njt = 2 * qi + 2;

    for (int jt = 0; jt < njt; jt++) {
        const int kv0 = jt * 64;
        __syncthreads();  // prior tile's ldsm reads done

        // ---- load K (normalized) and V (plain), split, store swizzled ----
#pragma unroll
        for (int it = 0; it < 4; it++) {
            int idx = tid + 256 * it;
            int row = idx >> 4, c4 = idx & 15;
            const size_t gb = (size_t)(kv0 + row) * DM + hoff + c4 * 4;
            uint32_t so = SWZ128(row * 128 + c4 * 8);

            float4 kv = *(const float4*)&kg[gb];
            float ss = kv.x * kv.x + kv.y * kv.y + kv.z * kv.z + kv.w * kv.w;
#pragma unroll
            for (int off = 1; off < 16; off <<= 1)
                ss += __shfl_xor_sync(0xffffffffu, ss, off);
            float inv = 1.0f / fmaxf(sqrtf(ss), 1e-12f);
            kv.x *= inv; kv.y *= inv; kv.z *= inv; kv.w *= inv;
            *(uint2*)(sm + 32768 + so) =
                make_uint2(pack2(kv.x, kv.y), pack2(kv.z, kv.w));
            *(uint2*)(sm + 40960 + so) =
                make_uint2(pack2(kv.x - bfr(kv.x), kv.y - bfr(kv.y)),
                           pack2(kv.z - bfr(kv.z), kv.w - bfr(kv.w)));

            float4 vv = *(const float4*)&vg[gb];
            *(uint2*)(sm + 49152 + so) =
                make_uint2(pack2(vv.x, vv.y), pack2(vv.z, vv.w));
            *(uint2*)(sm + 57344 + so) =
                make_uint2(pack2(vv.x - bfr(vv.x), vv.y - bfr(vv.y)),
                           pack2(vv.z - bfr(vv.z), vv.w - bfr(vv.w)));
        }
        __syncthreads();

        // warps 0-3 (rows q0..q0+63) skip the last kv tile: fully masked
        if (wid < 4 && jt == 2 * qi + 1) continue;

        // ---- S = Qh*Kh + Qh*Kl + Ql*Kh  (m16 x n64, k = 64) ----
        float c[8][4] = {};
#pragma unroll
        for (int ks = 0; ks < 4; ks++) {
            uint32_t ah[4], al[4];
            const uint32_t ao = SWZ128(
                (wid * 16 + ((lane >> 3) & 1) * 8 + (lane & 7)) * 128 +
                ks * 32 + (lane >> 4) * 16);
            ldsm4(uQh + ao, ah);
            ldsm4(uQl + ao, al);
#pragma unroll
            for (int np = 0; np < 4; np++) {
                uint32_t bh[4], bl[4];
                const uint32_t bo = SWZ128(
                    (np * 16 + (lane >> 4) * 8 + (lane & 7)) * 128 +
                    ks * 32 + ((lane >> 3) & 1) * 16);
                ldsm4(uKh + bo, bh);
                ldsm4(uKl + bo, bl);
                mma_bf16(c[2 * np + 0], ah, bh + 0);
                mma_bf16(c[2 * np + 0], ah, bl + 0);
                mma_bf16(c[2 * np + 0], al, bh + 0);
                mma_bf16(c[2 * np + 1], ah, bh + 2);
                mma_bf16(c[2 * np + 1], ah, bl + 2);
                mma_bf16(c[2 * np + 1], al, bh + 2);
            }
        }

        // ---- online softmax in registers ----
        float mx[2] = {-1e30f, -1e30f};
#pragma unroll
        for (int nt = 0; nt < 8; nt++) {
#pragma unroll
            for (int j = 0; j < 4; j++) {
                const int half = j >> 1, i = j & 1;
                const int key = kv0 + nt * 8 + (lane & 3) * 2 + i;
                float sv = c[nt][j] * 8.0f;
                if (key > row_lo + 8 * half) sv = -1e30f;
                c[nt][j] = sv;
                mx[half] = fmaxf(mx[half], sv);
            }
        }
#pragma unroll
        for (int half = 0; half < 2; half++) {
            mx[half] = fmaxf(mx[half], __shfl_xor_sync(0xffffffffu, mx[half], 1));
            mx[half] = fmaxf(mx[half], __shfl_xor_sync(0xffffffffu, mx[half], 2));
            float m_new = fmaxf(m_run[half], mx[half]);
            float fac = __expf(m_run[half] - m_new);
            m_run[half] = m_new;
            l_run[half] *= fac;
#pragma unroll
            for (int nt = 0; nt < 8; nt++) {
                o[nt][half * 2 + 0] *= fac;
                o[nt][half * 2 + 1] *= fac;
            }
        }
        float ts[2] = {0.0f, 0.0f};
#pragma unroll
        for (int nt = 0; nt < 8; nt++) {
#pragma unroll
            for (int j = 0; j < 4; j++) {
                float pv = __expf(c[nt][j] - m_run[j >> 1]);
                c[nt][j] = pv;
                ts[j >> 1] += pv;
            }
        }
#pragma unroll
        for (int half = 0; half < 2; half++) {
            ts[half] += __shfl_xor_sync(0xffffffffu, ts[half], 1);
            ts[half] += __shfl_xor_sync(0xffffffffu, ts[half], 2);
            l_run[half] += ts[half];
        }

        // ---- pack P into hi/lo A fragments (register identity, no smem) ----
        uint32_t ph[4][4], pl[4][4];
#pragma unroll
        for (int kt = 0; kt < 4; kt++) {
            const float* e = c[2 * kt];      // tile 2kt: j0..3
            const float* f = c[2 * kt + 1];  // tile 2kt+1
            ph[kt][0] = pack2(e[0], e[1]);
            ph[kt][1] = pack2(e[2], e[3]);
            ph[kt][2] = pack2(f[0], f[1]);
            ph[kt][3] = pack2(f[2], f[3]);
            pl[kt][0] = pack2(e[0] - bfr(e[0]), e[1] - bfr(e[1]));
            pl[kt][1] = pack2(e[2] - bfr(e[2]), e[3] - bfr(e[3]));
            pl[kt][2] = pack2(f[0] - bfr(f[0]), f[1] - bfr(f[1]));
            pl[kt][3] = pack2(f[2] - bfr(f[2]), f[3] - bfr(f[3]));
        }

        // ---- O += Ph*Vh + Ph*Vl + Pl*Vh  (B frags via trans-ldmatrix) ----
#pragma unroll
        for (int kt = 0; kt < 4; kt++) {
#pragma unroll
            for (int dp = 0; dp < 4; dp++) {
                uint32_t vh[4], vl[4];
                const uint32_t vo = SWZ128(
                    (kt * 16 + (lane & 15)) * 128 +
                    dp * 32 + (lane >> 4) * 16);
                ldsm4t(uVh + vo, vh);
                ldsm4t(uVl + vo, vl);
                mma_bf16(o[2 * dp + 0], ph[kt], vh + 0);
                mma_bf16(o[2 * dp + 0], ph[kt], vl + 0);
                mma_bf16(o[2 * dp + 0], pl[kt], vh + 0);
                mma_bf16(o[2 * dp + 1], ph[kt], vh + 2);
                mma_bf16(o[2 * dp + 1], ph[kt], vl + 2);
                mma_bf16(o[2 * dp + 1], pl[kt], vh + 2);
            }
        }
    }

    // ---- epilogue: O /= l, write fp32 ----
    const float inv0 = 1.0f / l_run[0];
    const float inv1 = 1.0f / l_run[1];
#pragma unroll
    for (int dt = 0; dt < 8; dt++) {
        const int col = (int)hoff + dt * 8 + (lane & 3) * 2;
        *(float2*)&og[(size_t)row_lo * DM + col] =
            make_float2(o[dt][0] * inv0, o[dt][1] * inv0);
        *(float2*)&og[(size_t)(row_lo + 8) * DM + col] =
            make_float2(o[dt][2] * inv1, o[dt][3] * inv1);
    }
}

// ---------------------------------------------------------------------------
extern "C" void kernel_launch(void* const* d_in, const int* in_sizes, int n_in,
                              void* d_out, int out_size)
{
    const float* x  = (const float*)d_in[0];
    const float* Wq = (const float*)d_in[1];
    const float* Wk = (const float*)d_in[2];
    const float* Wv = (const float*)d_in[3];
    const float* Wo = (const float*)d_in[4];
    float* out = (float*)d_out;

    float *q, *k, *v, *o;
    cudaGetSymbolAddress((void**)&q, g_q);
    cudaGetSymbolAddress((void**)&k, g_k);
    cudaGetSymbolAddress((void**)&v, g_v);
    cudaGetSymbolAddress((void**)&o, g_o);
    __nv_bfloat16 *xh, *xl, *oh, *ol, *wth, *wtl;
    cudaGetSymbolAddress((void**)&xh, g_xh);
    cudaGetSymbolAddress((void**)&xl, g_xl);
    cudaGetSymbolAddress((void**)&oh, g_oh);
    cudaGetSymbolAddress((void**)&ol, g_ol);
    cudaGetSymbolAddress((void**)&wth, g_wth);
    cudaGetSymbolAddress((void**)&wtl, g_wtl);

    cudaFuncSetAttribute(attn_mma_kernel,
                         cudaFuncAttributeMaxDynamicSharedMemorySize, ATTN_SMEM);

    const int nvec = N_TOK * DM / 4;
    dim3 gemm_grid(DM / 128, N_TOK / 128);

    split_kernel<<<nvec / 256, 256>>>(x, xh, xl);
    tsplit_kernel<<<dim3(32, 32, 4), dim3(32, 8)>>>(Wq, Wk, Wv, Wo, wth, wtl);
    gemm_mma_kernel<<<gemm_grid, 256>>>(xh, xl, wth + 0 * (size_t)DM * DM, wtl + 0 * (size_t)DM * DM, q);
    gemm_mma_kernel<<<gemm_grid, 256>>>(xh, xl, wth + 1 * (size_t)DM * DM, wtl + 1 * (size_t)DM * DM, k);
    gemm_mma_kernel<<<gemm_grid, 256>>>(xh, xl, wth + 2 * (size_t)DM * DM, wtl + 2 * (size_t)DM * DM, v);
    attn_mma_kernel<<<dim3(N_TOK / 128, NHEADS), 256, ATTN_SMEM>>>(q, k, v, o);
    split_kernel<<<nvec / 256, 256>>>(o, oh, ol);
    gemm_mma_kernel<<<gemm_grid, 256>>>(oh, ol, wth + 3 * (size_t)DM * DM, wtl + 3 * (size_t)DM * DM, out);
}

// round 8
// speedup vs baseline: 3.0208x; 1.4926x over previous
#include <cuda_runtime.h>
#include <cuda_bf16.h>
#include <cstdint>
#include <math.h>

#define N_TOK 4096
#define DM 1024
#define NHEADS 16
#define DH 64

// ---------------------------------------------------------------------------
// Scratch (allocation-free rule: __device__ globals)
// ---------------------------------------------------------------------------
__device__ float g_q[N_TOK * DM];
__device__ float g_k[N_TOK * DM];
__device__ float g_v[N_TOK * DM];

__device__ __nv_bfloat16 g_xh[N_TOK * DM];
__device__ __nv_bfloat16 g_xl[N_TOK * DM];
__device__ __nv_bfloat16 g_oh[N_TOK * DM];
__device__ __nv_bfloat16 g_ol[N_TOK * DM];
__device__ __nv_bfloat16 g_wth[4 * DM * DM];  // W^T hi: [w][n][k]
__device__ __nv_bfloat16 g_wtl[4 * DM * DM];  // W^T lo
// normalized/split attention operands, [head][tok][64]
__device__ __nv_bfloat16 g_qh[N_TOK * DM];
__device__ __nv_bfloat16 g_ql[N_TOK * DM];
__device__ __nv_bfloat16 g_kh[N_TOK * DM];
__device__ __nv_bfloat16 g_kl[N_TOK * DM];
__device__ __nv_bfloat16 g_vh[N_TOK * DM];
__device__ __nv_bfloat16 g_vl[N_TOK * DM];

#define SWZ64(o)  ((o) ^ (((o) >> 3) & 0x30))
#define SWZ128(o) ((o) ^ (((o) >> 3) & 0x70))

__device__ __forceinline__ uint32_t smem_u32(const void* p) {
    uint32_t a;
    asm("{ .reg .u64 t; cvta.to.shared.u64 t, %1; cvt.u32.u64 %0, t; }"
        : "=r"(a) : "l"(p));
    return a;
}
__device__ __forceinline__ void cpa16(uint32_t dst, const void* src) {
    asm volatile("cp.async.cg.shared.global [%0], [%1], 16;"
                 :: "r"(dst), "l"(src));
}
#define CPA_COMMIT() asm volatile("cp.async.commit_group;" ::: "memory")
#define CPA_WAIT0()  asm volatile("cp.async.wait_group 0;" ::: "memory")

__device__ __forceinline__ void ldsm4(uint32_t addr, uint32_t r[4]) {
    asm volatile("ldmatrix.sync.aligned.m8n8.x4.shared.b16 {%0,%1,%2,%3}, [%4];"
                 : "=r"(r[0]), "=r"(r[1]), "=r"(r[2]), "=r"(r[3]) : "r"(addr));
}
__device__ __forceinline__ void ldsm4t(uint32_t addr, uint32_t r[4]) {
    asm volatile("ldmatrix.sync.aligned.m8n8.x4.trans.shared.b16 {%0,%1,%2,%3}, [%4];"
                 : "=r"(r[0]), "=r"(r[1]), "=r"(r[2]), "=r"(r[3]) : "r"(addr));
}
__device__ __forceinline__ void ldsm2(uint32_t addr, uint32_t r[2]) {
    asm volatile("ldmatrix.sync.aligned.m8n8.x2.shared.b16 {%0,%1}, [%2];"
                 : "=r"(r[0]), "=r"(r[1]) : "r"(addr));
}
__device__ __forceinline__ void mma_bf16(float c[4], const uint32_t a[4],
                                         const uint32_t b[2]) {
    asm volatile(
        "mma.sync.aligned.m16n8k16.row.col.f32.bf16.bf16.f32 "
        "{%0,%1,%2,%3}, {%4,%5,%6,%7}, {%8,%9}, {%0,%1,%2,%3};"
        : "+f"(c[0]), "+f"(c[1]), "+f"(c[2]), "+f"(c[3])
        : "r"(a[0]), "r"(a[1]), "r"(a[2]), "r"(a[3]), "r"(b[0]), "r"(b[1]));
}
__device__ __forceinline__ uint32_t pack2(float a, float b) {
    uint32_t r;
    asm("cvt.rn.bf16x2.f32 %0, %1, %2;" : "=r"(r) : "f"(b), "f"(a));
    return r;
}
__device__ __forceinline__ float bfr(float x) {
    return __bfloat162float(__float2bfloat16(x));
}

// ---------------------------------------------------------------------------
// Split fp32 -> (hi, lo) bf16, elementwise (for x).
// ---------------------------------------------------------------------------
__global__ __launch_bounds__(256) void split_kernel(
    const float* __restrict__ src, __nv_bfloat16* __restrict__ h,
    __nv_bfloat16* __restrict__ l)
{
    int i = blockIdx.x * 256 + threadIdx.x;
    float4 v = ((const float4*)src)[i];
    ((uint32_t*)h)[2 * i + 0] = pack2(v.x, v.y);
    ((uint32_t*)h)[2 * i + 1] = pack2(v.z, v.w);
    ((uint32_t*)l)[2 * i + 0] = pack2(v.x - bfr(v.x), v.y - bfr(v.y));
    ((uint32_t*)l)[2 * i + 1] = pack2(v.z - bfr(v.z), v.w - bfr(v.w));
}

// ---------------------------------------------------------------------------
// Transpose + split all 4 weight matrices: out[w][n][k] = split(W_w[k][n]).
// ---------------------------------------------------------------------------
__global__ __launch_bounds__(256) void tsplit_kernel(
    const float* __restrict__ W0, const float* __restrict__ W1,
    const float* __restrict__ W2, const float* __restrict__ W3,
    __nv_bfloat16* __restrict__ H, __nv_bfloat16* __restrict__ L)
{
    const float* W = (blockIdx.z == 0) ? W0 : (blockIdx.z == 1) ? W1
                   : (blockIdx.z == 2) ? W2 : W3;
    __nv_bfloat16* h = H + (size_t)blockIdx.z * DM * DM;
    __nv_bfloat16* l = L + (size_t)blockIdx.z * DM * DM;
    __shared__ float t[32][33];
    const int bx = blockIdx.x * 32;
    const int by = blockIdx.y * 32;
    const int tx = threadIdx.x;
    for (int j = threadIdx.y; j < 32; j += 8)
        t[j][tx] = W[(size_t)(by + j) * DM + bx + tx];
    __syncthreads();
    for (int j = threadIdx.y; j < 32; j += 8) {
        float v = t[tx][j];
        __nv_bfloat16 hv = __float2bfloat16(v);
        __nv_bfloat16 lv = __float2bfloat16(v - __bfloat162float(hv));
        size_t idx = (size_t)(bx + j) * DM + by + tx;
        h[idx] = hv;
        l[idx] = lv;
    }
}

// ---------------------------------------------------------------------------
// Prep: q,k (l2norm) and v -> hi/lo bf16 in [head][tok][64] layout.
// One warp per (buf, tok, head).
// ---------------------------------------------------------------------------
__global__ __launch_bounds__(256) void qkv_prep_kernel(
    const float* __restrict__ q, const float* __restrict__ k,
    const float* __restrict__ v,
    __nv_bfloat16* __restrict__ qh, __nv_bfloat16* __restrict__ ql,
    __nv_bfloat16* __restrict__ kh, __nv_bfloat16* __restrict__ kl,
    __nv_bfloat16* __restrict__ vh, __nv_bfloat16* __restrict__ vl)
{
    const int gwarp = blockIdx.x * 8 + (threadIdx.x >> 5);
    const int lane = threadIdx.x & 31;
    const int buf = gwarp >> 16;           // 0=q, 1=k, 2=v
    const int rem = gwarp & 0xFFFF;
    const int head = rem & 15, tok = rem >> 4;

    const float* src = (buf == 0) ? q : (buf == 1) ? k : v;
    __nv_bfloat16* dh = (buf == 0) ? qh : (buf == 1) ? kh : vh;
    __nv_bfloat16* dl = (buf == 0) ? ql : (buf == 1) ? kl : vl;

    float2 val = *(const float2*)&src[(size_t)tok * DM + head * DH + lane * 2];
    if (buf < 2) {
        float ss = val.x * val.x + val.y * val.y;
#pragma unroll
        for (int off = 16; off > 0; off >>= 1)
            ss += __shfl_xor_sync(0xffffffffu, ss, off);
        float inv = 1.0f / fmaxf(sqrtf(ss), 1e-12f);
        val.x *= inv;
        val.y *= inv;
    }
    const size_t di = ((size_t)head * N_TOK + tok) * DH + lane * 2;
    ((uint32_t*)dh)[di >> 1] = pack2(val.x, val.y);
    ((uint32_t*)dl)[di >> 1] = pack2(val.x - bfr(val.x), val.y - bfr(val.y));
}

// ---------------------------------------------------------------------------
// HMMA split-bf16 GEMM with cp.async double buffering.
// C[M x 1024] = A @ B^T. CTA 128x128, BK=32, 8 warps (2m x 4n).
// Dynamic smem 64KB: 2 stages x (Ah|Al|Bh|Bl each 8KB).
// ---------------------------------------------------------------------------
#define GEMM_SMEM (2 * 32768)

__global__ __launch_bounds__(256, 2) void gemm_mma_kernel(
    const __nv_bfloat16* __restrict__ Ah, const __nv_bfloat16* __restrict__ Al,
    const __nv_bfloat16* __restrict__ Bh, const __nv_bfloat16* __restrict__ Bl,
    float* __restrict__ C)
{
    extern __shared__ char sm[];
    const uint32_t sbase = smem_u32(sm);

    const int tid = threadIdx.x;
    const int wid = tid >> 5, lane = tid & 31;
    const int wm = wid & 1, wn = wid >> 1;
    const int m0 = blockIdx.y * 128, n0 = blockIdx.x * 128;

    const int a_row = ((lane >> 3) & 1) * 8 + (lane & 7);
    const int a_kb  = (lane >> 4) * 16;
    const int l15 = lane & 15;
    const int b_row = l15 & 7;
    const int b_kb  = (l15 >> 3) * 16;

    // per-thread load coords (2 chunks of 16B per tile per stage)
    const int r_0 = tid >> 2, kb_0 = tid & 3;
    const int r_1 = (tid + 256) >> 2, kb_1 = (tid + 256) & 3;
    const uint32_t so_0 = SWZ64(r_0 * 64 + kb_0 * 16);
    const uint32_t so_1 = SWZ64(r_1 * 64 + kb_1 * 16);

    float c[4][4][4] = {};

#define GEMM_ISSUE(kc, s) do {                                                  \
    const int _k0 = (kc) * 32;                                                  \
    const uint32_t _b = sbase + (s) * 32768;                                    \
    const size_t _ga0 = (size_t)(m0 + r_0) * DM + _k0 + kb_0 * 8;               \
    const size_t _ga1 = (size_t)(m0 + r_1) * DM + _k0 + kb_1 * 8;               \
    const size_t _gb0 = (size_t)(n0 + r_0) * DM + _k0 + kb_0 * 8;               \
    const size_t _gb1 = (size_t)(n0 + r_1) * DM + _k0 + kb_1 * 8;               \
    cpa16(_b + so_0,             Ah + _ga0);                                    \
    cpa16(_b + so_1,             Ah + _ga1);                                    \
    cpa16(_b + 8192  + so_0,     Al + _ga0);                                    \
    cpa16(_b + 8192  + so_1,     Al + _ga1);                                    \
    cpa16(_b + 16384 + so_0,     Bh + _gb0);                                    \
    cpa16(_b + 16384 + so_1,     Bh + _gb1);                                    \
    cpa16(_b + 24576 + so_0,     Bl + _gb0);                                    \
    cpa16(_b + 24576 + so_1,     Bl + _gb1);                                    \
    CPA_COMMIT();                                                               \
} while (0)

    GEMM_ISSUE(0, 0);

    for (int kc = 0; kc < 32; kc++) {
        CPA_WAIT0();
        __syncthreads();
        if (kc < 31) GEMM_ISSUE(kc + 1, (kc + 1) & 1);

        const uint32_t uAh = sbase + (kc & 1) * 32768;
        const uint32_t uAl = uAh + 8192;
        const uint32_t uBh = uAh + 16384;
        const uint32_t uBl = uAh + 24576;

#pragma unroll
        for (int ks = 0; ks < 2; ks++) {
            uint32_t bh[4][2], bl[4][2];
#pragma unroll
            for (int nt = 0; nt < 4; nt++) {
                const uint32_t bo =
                    SWZ64((wn * 32 + nt * 8 + b_row) * 64 + ks * 32 + b_kb);
                ldsm2(uBh + bo, bh[nt]);
                ldsm2(uBl + bo, bl[nt]);
            }
#pragma unroll
            for (int mt = 0; mt < 4; mt++) {
                uint32_t ah[4], al[4];
                const uint32_t ao =
                    SWZ64((wm * 64 + mt * 16 + a_row) * 64 + ks * 32 + a_kb);
                ldsm4(uAh + ao, ah);
                ldsm4(uAl + ao, al);
#pragma unroll
                for (int nt = 0; nt < 4; nt++) {
                    mma_bf16(c[mt][nt], ah, bh[nt]);
                    mma_bf16(c[mt][nt], ah, bl[nt]);
                    mma_bf16(c[mt][nt], al, bh[nt]);
                }
            }
        }
        __syncthreads();
    }

    const int gq = lane >> 2, tq = lane & 3;
#pragma unroll
    for (int mt = 0; mt < 4; mt++) {
#pragma unroll
        for (int nt = 0; nt < 4; nt++) {
            const int row = m0 + wm * 64 + mt * 16 + gq;
            const int col = n0 + wn * 32 + nt * 8 + tq * 2;
            *(float2*)&C[(size_t)row * DM + col] =
                make_float2(c[mt][nt][0], c[mt][nt][1]);
            *(float2*)&C[(size_t)(row + 8) * DM + col] =
                make_float2(c[mt][nt][2], c[mt][nt][3]);
        }
    }
}

// ---------------------------------------------------------------------------
// Tensor-core causal flash attention, prepped bf16 inputs, cp.async
// double-buffered KV. Block = (q-tile 128, head), 8 warps (m16 each).
// Dynamic smem 96KB: Qh 16K | Ql 16K | 2 stages x (Kh|Kl|Vh|Vl each 8K).
// Writes split bf16 output directly to oh/ol [tok][1024].
// ---------------------------------------------------------------------------
#define ATTN_SMEM (32768 + 2 * 32768)

__global__ __launch_bounds__(256, 1) void attn_mma_kernel(
    const __nv_bfloat16* __restrict__ qh, const __nv_bfloat16* __restrict__ ql,
    const __nv_bfloat16* __restrict__ kh, const __nv_bfloat16* __restrict__ kl,
    const __nv_bfloat16* __restrict__ vh, const __nv_bfloat16* __restrict__ vl,
    __nv_bfloat16* __restrict__ oh, __nv_bfloat16* __restrict__ ol)
{
    extern __shared__ char sm[];
    const uint32_t sb = smem_u32(sm);
    const uint32_t uQh = sb, uQl = sb + 16384;

    const int tid = threadIdx.x, wid = tid >> 5, lane = tid & 31;
    const int h = blockIdx.y;
    const int qi = gridDim.x - 1 - blockIdx.x;
    const int q0 = qi * 128;
    const size_t hbase = (size_t)h * N_TOK * DH;  // bf16 elems

    // ---- load Q hi/lo tiles (each 128 rows x 128B), swizzled ----
    {
        const char* gqh = (const char*)(qh + hbase + (size_t)q0 * DH);
        const char* gql = (const char*)(ql + hbase + (size_t)q0 * DH);
#pragma unroll
        for (int it = 0; it < 4; it++) {
            int idx = tid + 256 * it;
            int row = idx >> 3, ck = idx & 7;
            uint32_t so = SWZ128(row * 128 + ck * 16);
            *(uint4*)(sm + so) = *(const uint4*)(gqh + row * 128 + ck * 16);
            *(uint4*)(sm + 16384 + so) = *(const uint4*)(gql + row * 128 + ck * 16);
        }
    }

    // per-thread KV load coords (2 chunks of 16B per buffer per stage)
    const int kr0 = tid >> 3, kc0 = tid & 7;
    const int kr1 = (tid + 256) >> 3, kc1 = (tid + 256) & 7;
    const uint32_t kso0 = SWZ128(kr0 * 128 + kc0 * 16);
    const uint32_t kso1 = SWZ128(kr1 * 128 + kc1 * 16);

#define ATTN_ISSUE(jt, s) do {                                                  \
    const size_t _tb = hbase + (size_t)((jt) * 64) * DH;                        \
    const char* _kh = (const char*)(kh + _tb);                                  \
    const char* _kl = (const char*)(kl + _tb);                                  \
    const char* _vh = (const char*)(vh + _tb);                                  \
    const char* _vl = (const char*)(vl + _tb);                                  \
    const uint32_t _b = sb + 32768 + (s) * 32768;                               \
    cpa16(_b + kso0,          _kh + kr0 * 128 + kc0 * 16);                      \
    cpa16(_b + kso1,          _kh + kr1 * 128 + kc1 * 16);                      \
    cpa16(_b + 8192 + kso0,   _kl + kr0 * 128 + kc0 * 16);                      \
    cpa16(_b + 8192 + kso1,   _kl + kr1 * 128 + kc1 * 16);                      \
    cpa16(_b + 16384 + kso0,  _vh + kr0 * 128 + kc0 * 16);                      \
    cpa16(_b + 16384 + kso1,  _vh + kr1 * 128 + kc1 * 16);                      \
    cpa16(_b + 24576 + kso0,  _vl + kr0 * 128 + kc0 * 16);                      \
    cpa16(_b + 24576 + kso1,  _vl + kr1 * 128 + kc1 * 16);                      \
    CPA_COMMIT();                                                               \
} while (0)

    float m_run[2] = {-1e30f, -1e30f};
    float l_run[2] = {0.0f, 0.0f};
    float o[8][4] = {};

    const int row_lo = q0 + wid * 16 + (lane >> 2);
    const int njt = 2 * qi + 2;

    ATTN_ISSUE(0, 0);

    for (int jt = 0; jt < njt; jt++) {
        const int kv0 = jt * 64;
        CPA_WAIT0();
        __syncthreads();
        if (jt + 1 < njt) ATTN_ISSUE(jt + 1, (jt + 1) & 1);

        // warps 0-3 (rows q0..q0+63): last kv tile fully masked — skip
        if (wid < 4 && jt == njt - 1) continue;

        const uint32_t uKh = sb + 32768 + (jt & 1) * 32768;
        const uint32_t uKl = uKh + 8192;
        const uint32_t uVh = uKh + 16384;
        const uint32_t uVl = uKh + 24576;

        // ---- S = Qh*Kh + Qh*Kl + Ql*Kh  (m16 x n64, k=64) ----
        float c[8][4] = {};
#pragma unroll
        for (int ks = 0; ks < 4; ks++) {
            uint32_t ah[4], al[4];
            const uint32_t ao = SWZ128(
                (wid * 16 + ((lane >> 3) & 1) * 8 + (lane & 7)) * 128 +
                ks * 32 + (lane >> 4) * 16);
            ldsm4(uQh + ao, ah);
            ldsm4(uQl + ao, al);
#pragma unroll
            for (int np = 0; np < 4; np++) {
                uint32_t bh[4], bl[4];
                const uint32_t bo = SWZ128(
                    (np * 16 + (lane >> 4) * 8 + (lane & 7)) * 128 +
                    ks * 32 + ((lane >> 3) & 1) * 16);
                ldsm4(uKh + bo, bh);
                ldsm4(uKl + bo, bl);
                mma_bf16(c[2 * np + 0], ah, bh + 0);
                mma_bf16(c[2 * np + 0], ah, bl + 0);
                mma_bf16(c[2 * np + 0], al, bh + 0);
                mma_bf16(c[2 * np + 1], ah, bh + 2);
                mma_bf16(c[2 * np + 1], ah, bl + 2);
                mma_bf16(c[2 * np + 1], al, bh + 2);
            }
        }

        // ---- online softmax in registers ----
        float mx[2] = {-1e30f, -1e30f};
#pragma unroll
        for (int nt = 0; nt < 8; nt++) {
#pragma unroll
            for (int j = 0; j < 4; j++) {
                const int half = j >> 1, i = j & 1;
                const int key = kv0 + nt * 8 + (lane & 3) * 2 + i;
                float sv = c[nt][j] * 8.0f;
                if (key > row_lo + 8 * half) sv = -1e30f;
                c[nt][j] = sv;
                mx[half] = fmaxf(mx[half], sv);
            }
        }
#pragma unroll
        for (int half = 0; half < 2; half++) {
            mx[half] = fmaxf(mx[half], __shfl_xor_sync(0xffffffffu, mx[half], 1));
            mx[half] = fmaxf(mx[half], __shfl_xor_sync(0xffffffffu, mx[half], 2));
            float m_new = fmaxf(m_run[half], mx[half]);
            float fac = __expf(m_run[half] - m_new);
            m_run[half] = m_new;
            l_run[half] *= fac;
#pragma unroll
            for (int nt = 0; nt < 8; nt++) {
                o[nt][half * 2 + 0] *= fac;
                o[nt][half * 2 + 1] *= fac;
            }
        }
        float ts[2] = {0.0f, 0.0f};
#pragma unroll
        for (int nt = 0; nt < 8; nt++) {
#pragma unroll
            for (int j = 0; j < 4; j++) {
                float pv = __expf(c[nt][j] - m_run[j >> 1]);
                c[nt][j] = pv;
                ts[j >> 1] += pv;
            }
        }
#pragma unroll
        for (int half = 0; half < 2; half++) {
            ts[half] += __shfl_xor_sync(0xffffffffu, ts[half], 1);
            ts[half] += __shfl_xor_sync(0xffffffffu, ts[half], 2);
            l_run[half] += ts[half];
        }

        // ---- pack P into hi/lo A fragments (registers only) ----
        uint32_t ph[4][4], pl[4][4];
#pragma unroll
        for (int kt = 0; kt < 4; kt++) {
            const float* e = c[2 * kt];
            const float* f = c[2 * kt + 1];
            ph[kt][0] = pack2(e[0], e[1]);
            ph[kt][1] = pack2(e[2], e[3]);
            ph[kt][2] = pack2(f[0], f[1]);
            ph[kt][3] = pack2(f[2], f[3]);
            pl[kt][0] = pack2(e[0] - bfr(e[0]), e[1] - bfr(e[1]));
            pl[kt][1] = pack2(e[2] - bfr(e[2]), e[3] - bfr(e[3]));
            pl[kt][2] = pack2(f[0] - bfr(f[0]), f[1] - bfr(f[1]));
            pl[kt][3] = pack2(f[2] - bfr(f[2]), f[3] - bfr(f[3]));
        }

        // ---- O += Ph*Vh + Ph*Vl + Pl*Vh ----
#pragma unroll
        for (int kt = 0; kt < 4; kt++) {
#pragma unroll
            for (int dp = 0; dp < 4; dp++) {
                uint32_t vhf[4], vlf[4];
                const uint32_t vo = SWZ128(
                    (kt * 16 + (lane & 15)) * 128 +
                    dp * 32 + (lane >> 4) * 16);
                ldsm4t(uVh + vo, vhf);
                ldsm4t(uVl + vo, vlf);
                mma_bf16(o[2 * dp + 0], ph[kt], vhf + 0);
                mma_bf16(o[2 * dp + 0], ph[kt], vlf + 0);
                mma_bf16(o[2 * dp + 0], pl[kt], vhf + 0);
                mma_bf16(o[2 * dp + 1], ph[kt], vhf + 2);
                mma_bf16(o[2 * dp + 1], ph[kt], vlf + 2);
                mma_bf16(o[2 * dp + 1], pl[kt], vhf + 2);
            }
        }
    }

    // ---- epilogue: O /= l, split to bf16 hi/lo, write [tok][1024] ----
    const float inv0 = 1.0f / l_run[0];
    const float inv1 = 1.0f / l_run[1];
    uint32_t* poh = (uint32_t*)oh;
    uint32_t* pol = (uint32_t*)ol;
#pragma unroll
    for (int dt = 0; dt < 8; dt++) {
        const int col = h * DH + dt * 8 + (lane & 3) * 2;
        float a0 = o[dt][0] * inv0, a1 = o[dt][1] * inv0;
        float b0 = o[dt][2] * inv1, b1 = o[dt][3] * inv1;
        const size_t i0 = ((size_t)row_lo * DM + col) >> 1;
        const size_t i1 = ((size_t)(row_lo + 8) * DM + col) >> 1;
        poh[i0] = pack2(a0, a1);
        pol[i0] = pack2(a0 - bfr(a0), a1 - bfr(a1));
        poh[i1] = pack2(b0, b1);
        pol[i1] = pack2(b0 - bfr(b0), b1 - bfr(b1));
    }
}

// ---------------------------------------------------------------------------
extern "C" void kernel_launch(void* const* d_in, const int* in_sizes, int n_in,
                              void* d_out, int out_size)
{
    const float* x  = (const float*)d_in[0];
    const float* Wq = (const float*)d_in[1];
    const float* Wk = (const float*)d_in[2];
    const float* Wv = (const float*)d_in[3];
    const float* Wo = (const float*)d_in[4];
    float* out = (float*)d_out;

    float *q, *k, *v;
    cudaGetSymbolAddress((void**)&q, g_q);
    cudaGetSymbolAddress((void**)&k, g_k);
    cudaGetSymbolAddress((void**)&v, g_v);
    __nv_bfloat16 *xh, *xl, *oh, *ol, *wth, *wtl;
    __nv_bfloat16 *qh, *ql, *kh, *kl, *vh, *vl;
    cudaGetSymbolAddress((void**)&xh, g_xh);
    cudaGetSymbolAddress((void**)&xl, g_xl);
    cudaGetSymbolAddress((void**)&oh, g_oh);
    cudaGetSymbolAddress((void**)&ol, g_ol);
    cudaGetSymbolAddress((void**)&wth, g_wth);
    cudaGetSymbolAddress((void**)&wtl, g_wtl);
    cudaGetSymbolAddress((void**)&qh, g_qh);
    cudaGetSymbolAddress((void**)&ql, g_ql);
    cudaGetSymbolAddress((void**)&kh, g_kh);
    cudaGetSymbolAddress((void**)&kl, g_kl);
    cudaGetSymbolAddress((void**)&vh, g_vh);
    cudaGetSymbolAddress((void**)&vl, g_vl);

    cudaFuncSetAttribute(gemm_mma_kernel,
                         cudaFuncAttributeMaxDynamicSharedMemorySize, GEMM_SMEM);
    cudaFuncSetAttribute(attn_mma_kernel,
                         cudaFuncAttributeMaxDynamicSharedMemorySize, ATTN_SMEM);

    const int nvec = N_TOK * DM / 4;
    dim3 gemm_grid(DM / 128, N_TOK / 128);

    split_kernel<<<nvec / 256, 256>>>(x, xh, xl);
    tsplit_kernel<<<dim3(32, 32, 4), dim3(32, 8)>>>(Wq, Wk, Wv, Wo, wth, wtl);
    gemm_mma_kernel<<<gemm_grid, 256, GEMM_SMEM>>>(xh, xl, wth + 0 * (size_t)DM * DM, wtl + 0 * (size_t)DM * DM, q);
    gemm_mma_kernel<<<gemm_grid, 256, GEMM_SMEM>>>(xh, xl, wth + 1 * (size_t)DM * DM, wtl + 1 * (size_t)DM * DM, k);
    gemm_mma_kernel<<<gemm_grid, 256, GEMM_SMEM>>>(xh, xl, wth + 2 * (size_t)DM * DM, wtl + 2 * (size_t)DM * DM, v);
    qkv_prep_kernel<<<3 * N_TOK * NHEADS / 8, 256>>>(q, k, v, qh, ql, kh, kl, vh, vl);
    attn_mma_kernel<<<dim3(N_TOK / 128, NHEADS), 256, ATTN_SMEM>>>(qh, ql, kh, kl, vh, vl, oh, ol);
    gemm_mma_kernel<<<gemm_grid, 256, GEMM_SMEM>>>(oh, ol, wth + 3 * (size_t)DM * DM, wtl + 3 * (size_t)DM * DM, out);
}